// round 5
// baseline (speedup 1.0000x reference)
#include <cuda_runtime.h>
#include <math.h>

// ---------------- scratch (no allocation allowed) ----------------
#define MAXN 256
#define MAXBLOCKS 8192

__device__ float g_partial[MAXBLOCKS * 2];
__device__ unsigned int g_count = 0;

// ---------------- tile config ----------------
#define TX 128          // tile width  (32 threads x 4 cols)
#define TY 32           // tile height (8 thread-rows x 4 rows/thread)
#define BDX 32
#define BDY 8
#define RPT 4
#define NTHR (BDX * BDY)
#define CULL_T 110.0f   // exp(-x) underflows to 0 in f32 for x > ~104; margin
#define LOG2E 1.4426950408889634f

__device__ __forceinline__ float ex2_approx(float x) {
    float r;
    asm("ex2.approx.ftz.f32 %0, %1;" : "=f"(r) : "f"(x));
    return r;
}
__device__ __forceinline__ float rcp_approx(float x) {
    float r;
    asm("rcp.approx.ftz.f32 %0, %1;" : "=f"(r) : "f"(x));
    return r;
}

// Single fused kernel:
//  phase A: per-block center param recompute (approx rcp) + exact tile cull
//  phase B: min-splat of gaussian log2-arguments, single EX2 epilogue, gts write
//  phase C: last-block-done deterministic final reduction -> out[0], out[1]
__global__ __launch_bounds__(NTHR)
void fused_kernel(const float* __restrict__ hm,
                  const float* __restrict__ sm,
                  const float* __restrict__ mask,
                  const float* __restrict__ gr,
                  const int*   __restrict__ centers,
                  float* __restrict__ gts,    // NOTE: only 8-byte aligned (d_out + 2)
                  float* __restrict__ out,
                  int H, int W, int N, int nblocks, float invCount) {
    int b  = blockIdx.z;
    int x0 = blockIdx.x * TX;
    int y0 = blockIdx.y * TY;
    int tid = threadIdx.y * BDX + threadIdx.x;

    __shared__ float scy[MAXN], scx[MAXN], sinv[MAXN];
    __shared__ int s_ns;
    if (tid == 0) s_ns = 0;
    __syncthreads();

    // ---- phase A: param compute + exact cull (closest point of tile rect) ----
    {
        float g  = __ldg(&gr[b]);
        float rg = rcp_approx(g);                   // ~2^-22 rel err, ok vs 1e-3
        float t  = 0.2f * rg;                       // PR_MIN / gr
        float fx0 = (float)x0;
        float fx1 = (float)min(x0 + TX - 1, W - 1);
        float fy0 = (float)y0;
        float fy1 = (float)min(y0 + TY - 1, H - 1);
        const int2* cptr = (const int2*)centers;
        int sbase = b * H * W;
        for (int i = tid; i < N; i += NTHR) {
            int2 c = __ldg(&cptr[b * N + i]);
            int cy = min(max(c.x, 0), H - 1);       // reference clamps both to H-1
            int cx = min(max(c.y, 0), H - 1);
            float smv = __ldg(&sm[sbase + cy * W + cx]);
            float relu = fmaxf(smv, 0.0f);
            float size = t + (relu * 0.2f) * rg;    // PR_MIN/gr + relu*RES/gr
            float inv = rcp_approx(2.0f * size * size);
            float fcx = (float)cx, fcy = (float)cy;
            float ddx = fmaxf(fmaxf(fx0 - fcx, fcx - fx1), 0.0f);
            float ddy = fmaxf(fmaxf(fy0 - fcy, fcy - fy1), 0.0f);
            float d2min = ddx * ddx + ddy * ddy;
            if (d2min * inv <= CULL_T) {            // cull in natural-log units
                int k = atomicAdd(&s_ns, 1);        // order-free: fmin is commutative/exact
                scy[k] = fcy; scx[k] = fcx;
                sinv[k] = inv * LOG2E;              // log2 units -> single EX2 later
            }
        }
    }
    __syncthreads();
    int ns = s_ns;

    // ---- phase B: each thread = 4 consecutive cols x 4 rows (stride BDY) ----
    int x4 = x0 + threadIdx.x * 4;
    int y  = y0 + threadIdx.y;          // rows y + r*BDY, r=0..3
    float fx = (float)x4;
    float fy = (float)y;

    float m[RPT][4];
#pragma unroll
    for (int r = 0; r < RPT; r++)
#pragma unroll
        for (int c = 0; c < 4; c++) m[r][c] = 1e30f;

    for (int i = 0; i < ns; i++) {
        float cx = scx[i], cy = scy[i], inv = sinv[i];
        float dx0 = fx - cx;
        float dx1 = dx0 + 1.0f, dx2 = dx0 + 2.0f, dx3 = dx0 + 3.0f;
        float b0 = dx0 * dx0 * inv;
        float b1 = dx1 * dx1 * inv;
        float b2 = dx2 * dx2 * inv;
        float b3 = dx3 * dx3 * inv;
        float dy0 = fy - cy;
#pragma unroll
        for (int r = 0; r < RPT; r++) {
            float dy = dy0 + (float)(r * BDY);
            float a = dy * dy * inv;
            m[r][0] = fminf(m[r][0], a + b0);
            m[r][1] = fminf(m[r][1], a + b1);
            m[r][2] = fminf(m[r][2], a + b2);
            m[r][3] = fminf(m[r][3], a + b3);
        }
    }

    // ---- epilogue: gt = 2^(-m), float4 input loads, float2 gts stores ----
    float lsum_hm = 0.0f, lsum_sm = 0.0f;
    int base = b * H * W;
    bool xok = (x4 + 3) < W;

#pragma unroll
    for (int r = 0; r < RPT; r++) {
        int yy = y + r * BDY;
        if (xok && yy < H) {
            int idx = base + yy * W + x4;
            float4 h4 = *(const float4*)(hm + idx);
            float4 k4 = *(const float4*)(mask + idx);
            float4 s4 = *(const float4*)(sm + idx);
            float4 g4;
            g4.x = ex2_approx(-m[r][0]);
            g4.y = ex2_approx(-m[r][1]);
            g4.z = ex2_approx(-m[r][2]);
            g4.w = ex2_approx(-m[r][3]);
            // gts is d_out+2 floats: 8B-aligned only -> two float2 stores
            *(float2*)(gts + idx)     = make_float2(g4.x, g4.y);
            *(float2*)(gts + idx + 2) = make_float2(g4.z, g4.w);
            float d;
            d = h4.x - g4.x; lsum_hm = fmaf(d * d, k4.x, lsum_hm);
            d = h4.y - g4.y; lsum_hm = fmaf(d * d, k4.y, lsum_hm);
            d = h4.z - g4.z; lsum_hm = fmaf(d * d, k4.z, lsum_hm);
            d = h4.w - g4.w; lsum_hm = fmaf(d * d, k4.w, lsum_hm);
            lsum_sm = fmaf(s4.x, s4.x, lsum_sm);
            lsum_sm = fmaf(s4.y, s4.y, lsum_sm);
            lsum_sm = fmaf(s4.z, s4.z, lsum_sm);
            lsum_sm = fmaf(s4.w, s4.w, lsum_sm);
        }
    }

    // ---- deterministic reduction: shuffle within warps, then thread 0 ----
    __shared__ float wh[NTHR / 32];
    __shared__ float ws[NTHR / 32];
    int lane = tid & 31;
    int wid  = tid >> 5;
#pragma unroll
    for (int off = 16; off > 0; off >>= 1) {
        lsum_hm += __shfl_down_sync(0xFFFFFFFFu, lsum_hm, off);
        lsum_sm += __shfl_down_sync(0xFFFFFFFFu, lsum_sm, off);
    }
    if (lane == 0) { wh[wid] = lsum_hm; ws[wid] = lsum_sm; }
    __syncthreads();

    __shared__ int isLast;
    if (tid == 0) {
        float th = 0.0f, ts = 0.0f;
#pragma unroll
        for (int i = 0; i < NTHR / 32; i++) { th += wh[i]; ts += ws[i]; }
        int blin = (b * gridDim.y + blockIdx.y) * gridDim.x + blockIdx.x;
        g_partial[2 * blin + 0] = th;
        g_partial[2 * blin + 1] = ts;
        __threadfence();
        unsigned int v = atomicAdd(&g_count, 1u);
        isLast = (v == (unsigned int)(nblocks - 1));
    }
    __syncthreads();

    // ---- phase C: last block does fixed-order final reduction ----
    if (isLast) {
        volatile float* vp = g_partial;
        float sh = 0.0f, ss = 0.0f;
        for (int i = tid; i < nblocks; i += NTHR) {
            sh += vp[2 * i + 0];
            ss += vp[2 * i + 1];
        }
        __shared__ float rh[NTHR];
        __shared__ float rs[NTHR];
        rh[tid] = sh; rs[tid] = ss;
        __syncthreads();
        for (int sft = NTHR / 2; sft > 0; sft >>= 1) {
            if (tid < sft) { rh[tid] += rh[tid + sft]; rs[tid] += rs[tid + sft]; }
            __syncthreads();
        }
        if (tid == 0) {
            out[0] = rs[0] * invCount;   // scale_loss = mean(sm^2)
            out[1] = rh[0] * invCount;   // hm_loss    = mean((hm-gt)^2 * mask)
            g_count = 0;                 // reset for next graph replay
        }
    }
}

extern "C" void kernel_launch(void* const* d_in, const int* in_sizes, int n_in,
                              void* d_out, int out_size) {
    const float* hm      = (const float*)d_in[0];
    const float* sm      = (const float*)d_in[1];
    const float* gr      = (const float*)d_in[2];
    const float* mask    = (const float*)d_in[3];
    const int*   centers = (const int*)  d_in[4];

    int B  = in_sizes[2];                 // ground_resolution: [B]
    int HW = in_sizes[0] / B;             // pred_hm: [B,1,H,W]
    int H  = 1;
    while ((long long)H * H < (long long)HW) H++;   // 512
    int W  = HW / H;
    int N  = in_sizes[4] / (2 * B);       // centers: [B,N,2]

    float* out = (float*)d_out;
    float* gts = out + (out_size - (size_t)B * HW); // tuple: [sl, hl, gts...]

    dim3 grid((W + TX - 1) / TX, (H + TY - 1) / TY, B);
    dim3 block(BDX, BDY);
    int nblocks = grid.x * grid.y * grid.z;
    fused_kernel<<<grid, block>>>(hm, sm, mask, gr, centers, gts, out,
                                  H, W, N, nblocks,
                                  1.0f / ((float)B * (float)HW));
}

// round 6
// speedup vs baseline: 1.3203x; 1.3203x over previous
#include <cuda_runtime.h>
#include <math.h>

// ---------------- scratch (no allocation allowed) ----------------
#define MAXN 256
#define MAXBLOCKS 8192

__device__ float g_partial[MAXBLOCKS * 2];
__device__ unsigned int g_count = 0;

// ---------------- tile config (reverted to R4 geometry: 1024 blocks) ----------------
#define TX 128          // tile width  (32 threads x 4 cols)
#define TY 16           // tile height (8 thread-rows x 2 rows/thread)
#define BDX 32
#define BDY 8
#define NTHR (BDX * BDY)
#define CULL_T 110.0f   // exp(-x) underflows to 0 in f32 for x > ~104; margin
#define LOG2E 1.4426950408889634f

__device__ __forceinline__ float ex2_approx(float x) {
    float r;
    asm("ex2.approx.ftz.f32 %0, %1;" : "=f"(r) : "f"(x));
    return r;
}
__device__ __forceinline__ float rcp_approx(float x) {
    float r;
    asm("rcp.approx.ftz.f32 %0, %1;" : "=f"(r) : "f"(x));
    return r;
}

// Single fused kernel:
//  prefetch: issue all 6 float4 input loads at entry (overlap DRAM latency with A+B)
//  phase A: per-block center param recompute (approx rcp) + exact tile cull
//  phase B: min-splat of gaussian log2-arguments, single EX2 epilogue, gts write
//  phase C: last-block-done deterministic final reduction -> out[0], out[1]
__global__ __launch_bounds__(NTHR)
void fused_kernel(const float* __restrict__ hm,
                  const float* __restrict__ sm,
                  const float* __restrict__ mask,
                  const float* __restrict__ gr,
                  const int*   __restrict__ centers,
                  float* __restrict__ gts,    // NOTE: only 8-byte aligned (d_out + 2)
                  float* __restrict__ out,
                  int H, int W, int N, int nblocks, float invCount) {
    int b  = blockIdx.z;
    int x0 = blockIdx.x * TX;
    int y0 = blockIdx.y * TY;
    int tid = threadIdx.y * BDX + threadIdx.x;

    // ---- prefetch: issue the bulk input loads FIRST (hide DRAM latency) ----
    int x4 = x0 + threadIdx.x * 4;
    int y  = y0 + threadIdx.y;              // rows y and y + BDY
    int base = b * H * W;
    int idx0 = base + y * W + x4;
    int idx1 = idx0 + BDY * W;
    bool ok0 = (x4 + 3) < W && y < H;
    bool ok1 = (x4 + 3) < W && (y + BDY) < H;

    float4 h0, k0, s0, h1, k1, s1;
    if (ok0) {
        h0 = *(const float4*)(hm + idx0);
        k0 = *(const float4*)(mask + idx0);
        s0 = *(const float4*)(sm + idx0);
    }
    if (ok1) {
        h1 = *(const float4*)(hm + idx1);
        k1 = *(const float4*)(mask + idx1);
        s1 = *(const float4*)(sm + idx1);
    }

    __shared__ float scy[MAXN], scx[MAXN], sinv[MAXN];
    __shared__ int s_ns;
    if (tid == 0) s_ns = 0;
    __syncthreads();

    // ---- phase A: param compute + exact cull (closest point of tile rect) ----
    {
        float g  = __ldg(&gr[b]);
        float rg = rcp_approx(g);                   // ~2^-22 rel err, ok vs 1e-3
        float t  = 0.2f * rg;                       // PR_MIN / gr
        float fx0 = (float)x0;
        float fx1 = (float)min(x0 + TX - 1, W - 1);
        float fy0 = (float)y0;
        float fy1 = (float)min(y0 + TY - 1, H - 1);
        const int2* cptr = (const int2*)centers;
        for (int i = tid; i < N; i += NTHR) {
            int2 c = __ldg(&cptr[b * N + i]);
            int cy = min(max(c.x, 0), H - 1);       // reference clamps both to H-1
            int cx = min(max(c.y, 0), H - 1);
            float smv = __ldg(&sm[base + cy * W + cx]);
            float relu = fmaxf(smv, 0.0f);
            float size = t + (relu * 0.2f) * rg;    // PR_MIN/gr + relu*RES/gr
            float inv = rcp_approx(2.0f * size * size);
            float fcx = (float)cx, fcy = (float)cy;
            float ddx = fmaxf(fmaxf(fx0 - fcx, fcx - fx1), 0.0f);
            float ddy = fmaxf(fmaxf(fy0 - fcy, fcy - fy1), 0.0f);
            float d2min = ddx * ddx + ddy * ddy;
            if (d2min * inv <= CULL_T) {            // cull in natural-log units
                int k = atomicAdd(&s_ns, 1);        // order-free: fmin is commutative/exact
                scy[k] = fcy; scx[k] = fcx;
                sinv[k] = inv * LOG2E;              // log2 units -> single EX2 later
            }
        }
    }
    __syncthreads();
    int ns = s_ns;

    // ---- phase B: each thread = 4 consecutive cols x 2 rows ----
    float fx = (float)x4;
    float fy = (float)y;

    float m00 = 1e30f, m01 = 1e30f, m02 = 1e30f, m03 = 1e30f;
    float m10 = 1e30f, m11 = 1e30f, m12 = 1e30f, m13 = 1e30f;

    for (int i = 0; i < ns; i++) {
        float cx = scx[i], cy = scy[i], inv = sinv[i];
        float dx0 = fx - cx;
        float dx1 = dx0 + 1.0f, dx2 = dx0 + 2.0f, dx3 = dx0 + 3.0f;
        float b0 = dx0 * dx0 * inv;
        float b1 = dx1 * dx1 * inv;
        float b2 = dx2 * dx2 * inv;
        float b3 = dx3 * dx3 * inv;
        float dy0 = fy - cy;
        float dy1 = dy0 + (float)BDY;
        float a0 = dy0 * dy0 * inv;
        float a1 = dy1 * dy1 * inv;
        m00 = fminf(m00, a0 + b0); m01 = fminf(m01, a0 + b1);
        m02 = fminf(m02, a0 + b2); m03 = fminf(m03, a0 + b3);
        m10 = fminf(m10, a1 + b0); m11 = fminf(m11, a1 + b1);
        m12 = fminf(m12, a1 + b2); m13 = fminf(m13, a1 + b3);
    }

    // ---- epilogue: gt = 2^(-m), consume prefetched inputs, float2 gts stores ----
    float lsum_hm = 0.0f, lsum_sm = 0.0f;

    if (ok0) {
        float4 g4;
        g4.x = ex2_approx(-m00);
        g4.y = ex2_approx(-m01);
        g4.z = ex2_approx(-m02);
        g4.w = ex2_approx(-m03);
        *(float2*)(gts + idx0)     = make_float2(g4.x, g4.y);
        *(float2*)(gts + idx0 + 2) = make_float2(g4.z, g4.w);
        float d;
        d = h0.x - g4.x; lsum_hm = fmaf(d * d, k0.x, lsum_hm);
        d = h0.y - g4.y; lsum_hm = fmaf(d * d, k0.y, lsum_hm);
        d = h0.z - g4.z; lsum_hm = fmaf(d * d, k0.z, lsum_hm);
        d = h0.w - g4.w; lsum_hm = fmaf(d * d, k0.w, lsum_hm);
        lsum_sm = fmaf(s0.x, s0.x, lsum_sm);
        lsum_sm = fmaf(s0.y, s0.y, lsum_sm);
        lsum_sm = fmaf(s0.z, s0.z, lsum_sm);
        lsum_sm = fmaf(s0.w, s0.w, lsum_sm);
    }
    if (ok1) {
        float4 g4;
        g4.x = ex2_approx(-m10);
        g4.y = ex2_approx(-m11);
        g4.z = ex2_approx(-m12);
        g4.w = ex2_approx(-m13);
        *(float2*)(gts + idx1)     = make_float2(g4.x, g4.y);
        *(float2*)(gts + idx1 + 2) = make_float2(g4.z, g4.w);
        float d;
        d = h1.x - g4.x; lsum_hm = fmaf(d * d, k1.x, lsum_hm);
        d = h1.y - g4.y; lsum_hm = fmaf(d * d, k1.y, lsum_hm);
        d = h1.z - g4.z; lsum_hm = fmaf(d * d, k1.z, lsum_hm);
        d = h1.w - g4.w; lsum_hm = fmaf(d * d, k1.w, lsum_hm);
        lsum_sm = fmaf(s1.x, s1.x, lsum_sm);
        lsum_sm = fmaf(s1.y, s1.y, lsum_sm);
        lsum_sm = fmaf(s1.z, s1.z, lsum_sm);
        lsum_sm = fmaf(s1.w, s1.w, lsum_sm);
    }

    // ---- deterministic reduction: shuffle within warps, then thread 0 ----
    __shared__ float wh[NTHR / 32];
    __shared__ float ws[NTHR / 32];
    int lane = tid & 31;
    int wid  = tid >> 5;
#pragma unroll
    for (int off = 16; off > 0; off >>= 1) {
        lsum_hm += __shfl_down_sync(0xFFFFFFFFu, lsum_hm, off);
        lsum_sm += __shfl_down_sync(0xFFFFFFFFu, lsum_sm, off);
    }
    if (lane == 0) { wh[wid] = lsum_hm; ws[wid] = lsum_sm; }
    __syncthreads();

    __shared__ int isLast;
    if (tid == 0) {
        float th = 0.0f, ts = 0.0f;
#pragma unroll
        for (int i = 0; i < NTHR / 32; i++) { th += wh[i]; ts += ws[i]; }
        int blin = (b * gridDim.y + blockIdx.y) * gridDim.x + blockIdx.x;
        g_partial[2 * blin + 0] = th;
        g_partial[2 * blin + 1] = ts;
        __threadfence();
        unsigned int v = atomicAdd(&g_count, 1u);
        isLast = (v == (unsigned int)(nblocks - 1));
    }
    __syncthreads();

    // ---- phase C: last block does fixed-order final reduction ----
    if (isLast) {
        volatile float* vp = g_partial;
        float sh = 0.0f, ss = 0.0f;
        for (int i = tid; i < nblocks; i += NTHR) {
            sh += vp[2 * i + 0];
            ss += vp[2 * i + 1];
        }
        __shared__ float rh[NTHR];
        __shared__ float rs[NTHR];
        rh[tid] = sh; rs[tid] = ss;
        __syncthreads();
        for (int sft = NTHR / 2; sft > 0; sft >>= 1) {
            if (tid < sft) { rh[tid] += rh[tid + sft]; rs[tid] += rs[tid + sft]; }
            __syncthreads();
        }
        if (tid == 0) {
            out[0] = rs[0] * invCount;   // scale_loss = mean(sm^2)
            out[1] = rh[0] * invCount;   // hm_loss    = mean((hm-gt)^2 * mask)
            g_count = 0;                 // reset for next graph replay
        }
    }
}

extern "C" void kernel_launch(void* const* d_in, const int* in_sizes, int n_in,
                              void* d_out, int out_size) {
    const float* hm      = (const float*)d_in[0];
    const float* sm      = (const float*)d_in[1];
    const float* gr      = (const float*)d_in[2];
    const float* mask    = (const float*)d_in[3];
    const int*   centers = (const int*)  d_in[4];

    int B  = in_sizes[2];                 // ground_resolution: [B]
    int HW = in_sizes[0] / B;             // pred_hm: [B,1,H,W]
    int H  = 1;
    while ((long long)H * H < (long long)HW) H++;   // 512
    int W  = HW / H;
    int N  = in_sizes[4] / (2 * B);       // centers: [B,N,2]

    float* out = (float*)d_out;
    float* gts = out + (out_size - (size_t)B * HW); // tuple: [sl, hl, gts...]

    dim3 grid((W + TX - 1) / TX, (H + TY - 1) / TY, B);
    dim3 block(BDX, BDY);
    int nblocks = grid.x * grid.y * grid.z;
    fused_kernel<<<grid, block>>>(hm, sm, mask, gr, centers, gts, out,
                                  H, W, N, nblocks,
                                  1.0f / ((float)B * (float)HW));
}

// round 8
// speedup vs baseline: 1.3268x; 1.0049x over previous
#include <cuda_runtime.h>
#include <cstdint>
#include <math.h>

// ---------------- scratch (no allocation allowed) ----------------
#define MAXN 256
#define MAXBLOCKS 8192

__device__ float g_partial[MAXBLOCKS * 2];
__device__ unsigned int g_count = 0;

// ---------------- tile config (R4 geometry: 1024 blocks) ----------------
#define TX 128          // tile width  (32 threads x 4 cols)
#define TY 16           // tile height (8 thread-rows x 2 rows/thread)
#define BDX 32
#define BDY 8
#define NTHR (BDX * BDY)
#define CULL_T 110.0f   // exp(-x) underflows to 0 in f32 for x > ~104; margin
#define LOG2E 1.4426950408889634f

__device__ __forceinline__ float ex2_approx(float x) {
    float r;
    asm("ex2.approx.ftz.f32 %0, %1;" : "=f"(r) : "f"(x));
    return r;
}
__device__ __forceinline__ float rcp_approx(float x) {
    float r;
    asm("rcp.approx.ftz.f32 %0, %1;" : "=f"(r) : "f"(x));
    return r;
}
__device__ __forceinline__ void cp_async16(unsigned int dst_smem, const void* src) {
    asm volatile("cp.async.cg.shared.global [%0], [%1], 16;" :: "r"(dst_smem), "l"(src));
}

// Single fused kernel:
//  prefetch: cp.async the 3 input tiles into smem at entry (zero register cost)
//  phase A: per-block center param recompute (approx rcp) + exact tile cull
//  phase B: min-splat of gaussian log2-arguments, single EX2 epilogue, gts write
//  phase C: last-block-done deterministic final reduction -> out[0], out[1]
__global__ __launch_bounds__(NTHR)
void fused_kernel(const float* __restrict__ hm,
                  const float* __restrict__ sm,
                  const float* __restrict__ mask,
                  const float* __restrict__ gr,
                  const int*   __restrict__ centers,
                  float* __restrict__ gts,    // NOTE: only 8-byte aligned (d_out + 2)
                  float* __restrict__ out,
                  int H, int W, int N, int nblocks, float invCount) {
    int b  = blockIdx.z;
    int x0 = blockIdx.x * TX;
    int y0 = blockIdx.y * TY;
    int tid = threadIdx.y * BDX + threadIdx.x;

    __shared__ float sh_h[TY * TX];
    __shared__ float sh_k[TY * TX];
    __shared__ float sh_s[TY * TX];
    __shared__ float scy[MAXN], scx[MAXN], sinv[MAXN];
    __shared__ int s_ns;

    // ---- prefetch: cp.async the 6 float4 input chunks into smem FIRST ----
    int x4 = x0 + threadIdx.x * 4;
    int y  = y0 + threadIdx.y;              // rows y and y + BDY
    int base = b * H * W;
    int idx0 = base + y * W + x4;
    int idx1 = idx0 + BDY * W;
    bool ok0 = (x4 + 3) < W && y < H;
    bool ok1 = (x4 + 3) < W && (y + BDY) < H;
    int toff0 = threadIdx.y * TX + threadIdx.x * 4;            // smem float index, row r=0
    int toff1 = toff0 + BDY * TX;                              // row r=1
    {
        unsigned int sh_h0 = (unsigned int)__cvta_generic_to_shared(sh_h);
        unsigned int sh_k0 = (unsigned int)__cvta_generic_to_shared(sh_k);
        unsigned int sh_s0 = (unsigned int)__cvta_generic_to_shared(sh_s);
        if (ok0) {
            cp_async16(sh_h0 + toff0 * 4, hm + idx0);
            cp_async16(sh_k0 + toff0 * 4, mask + idx0);
            cp_async16(sh_s0 + toff0 * 4, sm + idx0);
        }
        if (ok1) {
            cp_async16(sh_h0 + toff1 * 4, hm + idx1);
            cp_async16(sh_k0 + toff1 * 4, mask + idx1);
            cp_async16(sh_s0 + toff1 * 4, sm + idx1);
        }
        asm volatile("cp.async.commit_group;" ::: "memory");
    }

    if (tid == 0) s_ns = 0;
    __syncthreads();

    // ---- phase A: param compute + exact cull (closest point of tile rect) ----
    {
        float g  = __ldg(&gr[b]);
        float rg = rcp_approx(g);                   // ~2^-22 rel err, ok vs 1e-3
        float t  = 0.2f * rg;                       // PR_MIN / gr
        float fx0 = (float)x0;
        float fx1 = (float)min(x0 + TX - 1, W - 1);
        float fy0 = (float)y0;
        float fy1 = (float)min(y0 + TY - 1, H - 1);
        const int2* cptr = (const int2*)centers;
        for (int i = tid; i < N; i += NTHR) {
            int2 c = __ldg(&cptr[b * N + i]);
            int cy = min(max(c.x, 0), H - 1);       // reference clamps both to H-1
            int cx = min(max(c.y, 0), H - 1);
            float smv = __ldg(&sm[base + cy * W + cx]);
            float relu = fmaxf(smv, 0.0f);
            float size = t + (relu * 0.2f) * rg;    // PR_MIN/gr + relu*RES/gr
            float inv = rcp_approx(2.0f * size * size);
            float fcx = (float)cx, fcy = (float)cy;
            float ddx = fmaxf(fmaxf(fx0 - fcx, fcx - fx1), 0.0f);
            float ddy = fmaxf(fmaxf(fy0 - fcy, fcy - fy1), 0.0f);
            float d2min = ddx * ddx + ddy * ddy;
            if (d2min * inv <= CULL_T) {            // cull in natural-log units
                int k = atomicAdd(&s_ns, 1);        // order-free: fmin is commutative/exact
                scy[k] = fcy; scx[k] = fcx;
                sinv[k] = inv * LOG2E;              // log2 units -> single EX2 later
            }
        }
    }
    __syncthreads();
    int ns = s_ns;

    // ---- phase B: each thread = 4 consecutive cols x 2 rows ----
    float fx = (float)x4;
    float fy = (float)y;

    float m00 = 1e30f, m01 = 1e30f, m02 = 1e30f, m03 = 1e30f;
    float m10 = 1e30f, m11 = 1e30f, m12 = 1e30f, m13 = 1e30f;

    for (int i = 0; i < ns; i++) {
        float cx = scx[i], cy = scy[i], inv = sinv[i];
        float dx0 = fx - cx;
        float dx1 = dx0 + 1.0f, dx2 = dx0 + 2.0f, dx3 = dx0 + 3.0f;
        float b0 = dx0 * dx0 * inv;
        float b1 = dx1 * dx1 * inv;
        float b2 = dx2 * dx2 * inv;
        float b3 = dx3 * dx3 * inv;
        float dy0 = fy - cy;
        float dy1 = dy0 + (float)BDY;
        float a0 = dy0 * dy0 * inv;
        float a1 = dy1 * dy1 * inv;
        m00 = fminf(m00, a0 + b0); m01 = fminf(m01, a0 + b1);
        m02 = fminf(m02, a0 + b2); m03 = fminf(m03, a0 + b3);
        m10 = fminf(m10, a1 + b0); m11 = fminf(m11, a1 + b1);
        m12 = fminf(m12, a1 + b2); m13 = fminf(m13, a1 + b3);
    }

    // ---- epilogue: wait prefetch, gt = 2^(-m), losses, float2 gts stores ----
    asm volatile("cp.async.wait_group 0;" ::: "memory");
    // each thread reads only its own slots -> no barrier needed

    float lsum_hm = 0.0f, lsum_sm = 0.0f;

    if (ok0) {
        float4 h4 = *(const float4*)(sh_h + toff0);
        float4 k4 = *(const float4*)(sh_k + toff0);
        float4 s4 = *(const float4*)(sh_s + toff0);
        float4 g4;
        g4.x = ex2_approx(-m00);
        g4.y = ex2_approx(-m01);
        g4.z = ex2_approx(-m02);
        g4.w = ex2_approx(-m03);
        *(float2*)(gts + idx0)     = make_float2(g4.x, g4.y);
        *(float2*)(gts + idx0 + 2) = make_float2(g4.z, g4.w);
        float d;
        d = h4.x - g4.x; lsum_hm = fmaf(d * d, k4.x, lsum_hm);
        d = h4.y - g4.y; lsum_hm = fmaf(d * d, k4.y, lsum_hm);
        d = h4.z - g4.z; lsum_hm = fmaf(d * d, k4.z, lsum_hm);
        d = h4.w - g4.w; lsum_hm = fmaf(d * d, k4.w, lsum_hm);
        lsum_sm = fmaf(s4.x, s4.x, lsum_sm);
        lsum_sm = fmaf(s4.y, s4.y, lsum_sm);
        lsum_sm = fmaf(s4.z, s4.z, lsum_sm);
        lsum_sm = fmaf(s4.w, s4.w, lsum_sm);
    }
    if (ok1) {
        float4 h4 = *(const float4*)(sh_h + toff1);
        float4 k4 = *(const float4*)(sh_k + toff1);
        float4 s4 = *(const float4*)(sh_s + toff1);
        float4 g4;
        g4.x = ex2_approx(-m10);
        g4.y = ex2_approx(-m11);
        g4.z = ex2_approx(-m12);
        g4.w = ex2_approx(-m13);
        *(float2*)(gts + idx1)     = make_float2(g4.x, g4.y);
        *(float2*)(gts + idx1 + 2) = make_float2(g4.z, g4.w);
        float d;
        d = h4.x - g4.x; lsum_hm = fmaf(d * d, k4.x, lsum_hm);
        d = h4.y - g4.y; lsum_hm = fmaf(d * d, k4.y, lsum_hm);
        d = h4.z - g4.z; lsum_hm = fmaf(d * d, k4.z, lsum_hm);
        d = h4.w - g4.w; lsum_hm = fmaf(d * d, k4.w, lsum_hm);
        lsum_sm = fmaf(s4.x, s4.x, lsum_sm);
        lsum_sm = fmaf(s4.y, s4.y, lsum_sm);
        lsum_sm = fmaf(s4.z, s4.z, lsum_sm);
        lsum_sm = fmaf(s4.w, s4.w, lsum_sm);
    }

    // ---- deterministic reduction: shuffle within warps, then thread 0 ----
    __shared__ float wh[NTHR / 32];
    __shared__ float ws[NTHR / 32];
    int lane = tid & 31;
    int wid  = tid >> 5;
#pragma unroll
    for (int off = 16; off > 0; off >>= 1) {
        lsum_hm += __shfl_down_sync(0xFFFFFFFFu, lsum_hm, off);
        lsum_sm += __shfl_down_sync(0xFFFFFFFFu, lsum_sm, off);
    }
    if (lane == 0) { wh[wid] = lsum_hm; ws[wid] = lsum_sm; }
    __syncthreads();

    __shared__ int isLast;
    if (tid == 0) {
        float th = 0.0f, ts = 0.0f;
#pragma unroll
        for (int i = 0; i < NTHR / 32; i++) { th += wh[i]; ts += ws[i]; }
        int blin = (b * gridDim.y + blockIdx.y) * gridDim.x + blockIdx.x;
        g_partial[2 * blin + 0] = th;
        g_partial[2 * blin + 1] = ts;
        __threadfence();
        unsigned int v = atomicAdd(&g_count, 1u);
        isLast = (v == (unsigned int)(nblocks - 1));
    }
    __syncthreads();

    // ---- phase C: last block does fixed-order final reduction ----
    if (isLast) {
        volatile float* vp = g_partial;
        float sh = 0.0f, ss = 0.0f;
        for (int i = tid; i < nblocks; i += NTHR) {
            sh += vp[2 * i + 0];
            ss += vp[2 * i + 1];
        }
        __shared__ float rh[NTHR];
        __shared__ float rs[NTHR];
        rh[tid] = sh; rs[tid] = ss;
        __syncthreads();
        for (int sft = NTHR / 2; sft > 0; sft >>= 1) {
            if (tid < sft) { rh[tid] += rh[tid + sft]; rs[tid] += rs[tid + sft]; }
            __syncthreads();
        }
        if (tid == 0) {
            out[0] = rs[0] * invCount;   // scale_loss = mean(sm^2)
            out[1] = rh[0] * invCount;   // hm_loss    = mean((hm-gt)^2 * mask)
            g_count = 0;                 // reset for next graph replay
        }
    }
}

extern "C" void kernel_launch(void* const* d_in, const int* in_sizes, int n_in,
                              void* d_out, int out_size) {
    const float* hm      = (const float*)d_in[0];
    const float* sm      = (const float*)d_in[1];
    const float* gr      = (const float*)d_in[2];
    const float* mask    = (const float*)d_in[3];
    const int*   centers = (const int*)  d_in[4];

    int B  = in_sizes[2];                 // ground_resolution: [B]
    int HW = in_sizes[0] / B;             // pred_hm: [B,1,H,W]
    int H  = 1;
    while ((long long)H * H < (long long)HW) H++;   // 512
    int W  = HW / H;
    int N  = in_sizes[4] / (2 * B);       // centers: [B,N,2]

    float* out = (float*)d_out;
    float* gts = out + (out_size - (size_t)B * HW); // tuple: [sl, hl, gts...]

    dim3 grid((W + TX - 1) / TX, (H + TY - 1) / TY, B);
    dim3 block(BDX, BDY);
    int nblocks = grid.x * grid.y * grid.z;
    fused_kernel<<<grid, block>>>(hm, sm, mask, gr, centers, gts, out,
                                  H, W, N, nblocks,
                                  1.0f / ((float)B * (float)HW));
}